// round 13
// baseline (speedup 1.0000x reference)
#include <cuda_runtime.h>
#include <cuda_fp16.h>
#include <cstdint>
#include <cstddef>

// Biaffine: out[b,x,y,o] = sum_ij in1[b,x,i] w1[i,o,j] in2[b,y,j] + p + q + bias
//   stage1: U' = in1_hi @ w1_hi^T (+ w2b^T folded -> q) ; p-tile = in1 @ w2a
//           fp16-accumulate HMMA, promoted to fp32 every 64-K segment
//   stage2: out = U' @ in2_hi^T + (p + bias)   (fp32-accumulate)
// CTA 128x128, 256 thr (8 warps 2x4, warp 64x32), 4-buffer cp.async ring.

#define B_ 8
#define L_ 256
#define D_ 512
#define O_ 128
#define NCH 16                  // 512 / 32
#define TBUF 10240              // 128 rows * 80B
#define CBUF (2 * TBUF)         // A + B tiles per chunk buffer
#define SMEM_BYTES 81920        // 4 * CBUF (epilogues fit inside)

using hf = __half;

// -------------------- device globals (no runtime alloc) --------------------
__device__ __align__(128) hf g_Ahi[2048 * 512];
__device__ __align__(128) hf g_I2hi[2048 * 512];
__device__ __align__(128) hf g_Whi[(size_t)65536 * 512];
__device__ __align__(128) hf g_Uhi[(size_t)262144 * 512];
__device__ __align__(128) hf g_W2aT[128 * 512];     // [o][i] fp16 (p-tile B operand)
__device__ __align__(128) float g_W2bT[128 * 512];  // [o][j] fp32 (U epilogue addend)
__device__ __align__(128) float g_p[2048 * 128];

// -------------------- helpers --------------------
__device__ __forceinline__ uint32_t smem_u32(const void* p) {
    uint32_t a;
    asm("{ .reg .u64 t; cvta.to.shared.u64 t, %1; cvt.u32.u64 %0, t; }" : "=r"(a) : "l"(p));
    return a;
}
__device__ __forceinline__ void cpa16(uint32_t s, const void* g) {
    asm volatile("cp.async.cg.shared.global [%0], [%1], 16;" :: "r"(s), "l"(g));
}
#define CP_COMMIT asm volatile("cp.async.commit_group;" ::: "memory")
#define CP_WAIT2  asm volatile("cp.async.wait_group 2;" ::: "memory")
#define CP_WAIT1  asm volatile("cp.async.wait_group 1;" ::: "memory")
#define CP_WAIT0  asm volatile("cp.async.wait_group 0;" ::: "memory")

__device__ __forceinline__ void ldmx4(uint32_t* r, uint32_t addr) {
    asm volatile("ldmatrix.sync.aligned.m8n8.x4.shared.b16 {%0,%1,%2,%3}, [%4];"
                 : "=r"(r[0]), "=r"(r[1]), "=r"(r[2]), "=r"(r[3]) : "r"(addr));
}
__device__ __forceinline__ void mma16816_f32(float* c, const uint32_t* a, uint32_t b0, uint32_t b1) {
    asm("mma.sync.aligned.m16n8k16.row.col.f32.f16.f16.f32 "
        "{%0,%1,%2,%3},{%4,%5,%6,%7},{%8,%9},{%0,%1,%2,%3};"
        : "+f"(c[0]), "+f"(c[1]), "+f"(c[2]), "+f"(c[3])
        : "r"(a[0]), "r"(a[1]), "r"(a[2]), "r"(a[3]), "r"(b0), "r"(b1));
}
__device__ __forceinline__ void mma16816_f16(uint32_t* c, const uint32_t* a, uint32_t b0, uint32_t b1) {
    asm("mma.sync.aligned.m16n8k16.row.col.f16.f16.f16.f16 "
        "{%0,%1},{%2,%3,%4,%5},{%6,%7},{%0,%1};"
        : "+r"(c[0]), "+r"(c[1])
        : "r"(a[0]), "r"(a[1]), "r"(a[2]), "r"(a[3]), "r"(b0), "r"(b1));
}

// -------------------- chunk loader: A + B tiles 128x32 fp16 (256 thr) -------
__device__ __forceinline__ void load2(uint32_t sbase, int buf,
                                      const hf* __restrict__ ta,
                                      const hf* __restrict__ tb,
                                      int kcol, int t) {
    const int r = t >> 2, c = t & 3;               // r 0..63, c 0..3
    const uint32_t so = sbase + buf * CBUF + r * 80 + c * 16;
    const size_t go = (size_t)r * 512 + kcol + c * 8;
    const hf* ga = ta + go;
    const hf* gb = tb + go;
    cpa16(so, ga);
    cpa16(so + 64 * 80, ga + (size_t)64 * 512);
    cpa16(so + TBUF, gb);
    cpa16(so + TBUF + 64 * 80, gb + (size_t)64 * 512);
}

// -------------------- fragment load (warp tile 64x32) --------------------
__device__ __forceinline__ void ld_frags(uint32_t sbase, int buf, int kst,
                                         int wm, int wn, uint32_t lro,
                                         uint32_t ar[4][4], uint32_t br[2][4]) {
    const uint32_t sA = sbase + buf * CBUF + wm * (64 * 80) + lro + kst * 32;
    const uint32_t sB = sbase + buf * CBUF + TBUF + wn * (32 * 80) + lro + kst * 32;
#pragma unroll
    for (int mt = 0; mt < 4; mt++) ldmx4(ar[mt], sA + mt * (16 * 80));
#pragma unroll
    for (int n2 = 0; n2 < 2; n2++) ldmx4(br[n2], sB + n2 * (16 * 80));
}

// -------------------- shared mainloop (templated accumulate mode) ----------
// 4-buffer ring: iteration c loads buf (c+3)&3. HACC: fp16 acc, promoted to
// fp32 every 2 chunks (64 K).
template <bool HACC>
__device__ __forceinline__ void mma_mainloop(char* smem,
                                             const hf* pa, const hf* pb,
                                             float acc[4][4][4],
                                             int wm, int wn, int lane, int t) {
    const uint32_t sbase = smem_u32(smem);
    const uint32_t lro = (lane & 15) * 80 + (lane >> 4) * 16;

    uint32_t ar[4][4], br[2][4];
    uint32_t acch[4][4][2];
    if (HACC) {
#pragma unroll
        for (int i = 0; i < 4; i++)
#pragma unroll
            for (int j = 0; j < 4; j++) { acch[i][j][0] = 0u; acch[i][j][1] = 0u; }
    }

    load2(sbase, 0, pa, pb, 0, t);  CP_COMMIT;
    load2(sbase, 1, pa, pb, 32, t); CP_COMMIT;
    load2(sbase, 2, pa, pb, 64, t); CP_COMMIT;

#pragma unroll
    for (int c = 0; c < NCH; c++) {
        if (c <= NCH - 3)      { CP_WAIT2; }
        else if (c == NCH - 2) { CP_WAIT1; }
        else                   { CP_WAIT0; }
        __syncthreads();        // all warps past iter c-1; buf (c+3)&3 free

        if (c + 3 < NCH) { load2(sbase, (c + 3) & 3, pa, pb, (c + 3) * 32, t); CP_COMMIT; }

        const int buf = c & 3;
#pragma unroll
        for (int kst = 0; kst < 2; kst++) {
            ld_frags(sbase, buf, kst, wm, wn, lro, ar, br);
#pragma unroll
            for (int mt = 0; mt < 4; mt++)
#pragma unroll
                for (int n2 = 0; n2 < 2; n2++) {
                    if (HACC) {
                        mma16816_f16(acch[mt][n2 * 2 + 0], ar[mt], br[n2][0], br[n2][2]);
                        mma16816_f16(acch[mt][n2 * 2 + 1], ar[mt], br[n2][1], br[n2][3]);
                    } else {
                        mma16816_f32(acc[mt][n2 * 2 + 0], ar[mt], br[n2][0], br[n2][2]);
                        mma16816_f32(acc[mt][n2 * 2 + 1], ar[mt], br[n2][1], br[n2][3]);
                    }
                }
        }

        if (HACC && (c & 1)) {
            // promote fp16 segment accumulators into fp32, reset fp16
#pragma unroll
            for (int mt = 0; mt < 4; mt++)
#pragma unroll
                for (int nt = 0; nt < 4; nt++) {
                    float2 f0 = __half22float2(*(__half2*)&acch[mt][nt][0]);
                    float2 f1 = __half22float2(*(__half2*)&acch[mt][nt][1]);
                    acc[mt][nt][0] += f0.x;
                    acc[mt][nt][1] += f0.y;
                    acc[mt][nt][2] += f1.x;
                    acc[mt][nt][3] += f1.y;
                    acch[mt][nt][0] = 0u;
                    acch[mt][nt][1] = 0u;
                }
        }
    }
}

// -------------------- stage 1: U' = Ahi @ Whi^T + w2b^T; p-tile at by==512 --
// grid (16, 513): x = m-tile (2048/128), y = n-tile (65536/128) or p-tile
__global__ __launch_bounds__(256, 1) void stage1_mma() {
    extern __shared__ char smem[];
    const int t = threadIdx.x, lane = t & 31, wid = t >> 5;
    const int wm = wid & 1, wn = wid >> 1;          // wm 0..1 (M64), wn 0..3 (N32)
    const int g = lane >> 2, qp = lane & 3;

    const size_t m0 = (size_t)blockIdx.x * 128;
    const int by = blockIdx.y;
    const bool ptile = (by == 512);
    const int n0 = ptile ? 0 : by * 128;
    const int o = n0 >> 9, j0 = n0 & 511;

    float acc[4][4][4];
#pragma unroll
    for (int i = 0; i < 4; i++)
#pragma unroll
        for (int j = 0; j < 4; j++)
#pragma unroll
            for (int k = 0; k < 4; k++) acc[i][j][k] = 0.f;

    const hf* pb = ptile ? g_W2aT : (g_Whi + (size_t)n0 * 512);
    mma_mainloop<true>(smem, g_Ahi + m0 * 512, pb, acc, wm, wn, lane, t);

    if (ptile) {
        // p[m][o] = acc, fp32 direct stores (16 CTAs total)
#pragma unroll
        for (int mt = 0; mt < 4; mt++) {
            const int r = wm * 64 + mt * 16 + g;
#pragma unroll
            for (int nt = 0; nt < 4; nt++) {
                const int col = wn * 32 + nt * 8 + qp * 2;
                float* d0 = &g_p[(m0 + r) * 128 + col];
                d0[0] = acc[mt][nt][0];
                d0[1] = acc[mt][nt][1];
                float* d1 = &g_p[(m0 + r + 8) * 128 + col];
                d1[0] = acc[mt][nt][2];
                d1[1] = acc[mt][nt][3];
            }
        }
        return;
    }

    // fold q: add w2b^T[o][j0+col]
    float wb[4][2];
#pragma unroll
    for (int nt = 0; nt < 4; nt++) {
        const int col = wn * 32 + nt * 8 + qp * 2;
        wb[nt][0] = g_W2bT[o * 512 + j0 + col];
        wb[nt][1] = g_W2bT[o * 512 + j0 + col + 1];
    }

    // epilogue: fp32 acc (+w2b) -> fp16, staged in smem (272B stride)
    __syncthreads();
#pragma unroll
    for (int mt = 0; mt < 4; mt++) {
        const int r = wm * 64 + mt * 16 + g;
#pragma unroll
        for (int nt = 0; nt < 4; nt++) {
            const int col = wn * 32 + nt * 8 + qp * 2;
            *(half2*)(smem + r * 272 + col * 2) =
                __floats2half2_rn(acc[mt][nt][0] + wb[nt][0], acc[mt][nt][1] + wb[nt][1]);
            *(half2*)(smem + (r + 8) * 272 + col * 2) =
                __floats2half2_rn(acc[mt][nt][2] + wb[nt][0], acc[mt][nt][3] + wb[nt][1]);
        }
    }
    __syncthreads();
#pragma unroll
    for (int i = 0; i < 8; i++) {
        const int idx = t + i * 256;
        const int r = idx >> 4, colq = idx & 15;
        uint4 v = *(uint4*)(smem + r * 272 + colq * 16);
        *(uint4*)(g_Uhi + ((m0 + r) * 128 + o) * 512 + j0 + colq * 8) = v;
    }
}

// -------------------- stage 2: out = U' @ I2hi^T + (p + bias) ----
// grid (2, 256, 8): x = y-tile, y = x index, z = b  (fp32 accumulate)
__global__ __launch_bounds__(256, 2) void stage2_mma(const float* __restrict__ w2,
                                                     float* __restrict__ out) {
    extern __shared__ char smem[];
    __shared__ float pb_s[128];
    const int t = threadIdx.x, lane = t & 31, wid = t >> 5;
    const int wm = wid & 1, wn = wid >> 1;
    const int g = lane >> 2, qp = lane & 3;

    const int b = blockIdx.z, x = blockIdx.y, n0 = blockIdx.x * 128;
    const size_t a_row0 = ((size_t)b * L_ + x) * 128;   // U rows (o)
    const size_t b_row0 = (size_t)b * L_ + n0;          // in2 rows (y)

    float acc[4][4][4];
#pragma unroll
    for (int i = 0; i < 4; i++)
#pragma unroll
        for (int j = 0; j < 4; j++)
#pragma unroll
            for (int k = 0; k < 4; k++) acc[i][j][k] = 0.f;

    mma_mainloop<false>(smem, g_Uhi + a_row0 * 512, g_I2hi + b_row0 * 512, acc, wm, wn, lane, t);

    __syncthreads();
    if (t < 128) pb_s[t] = g_p[((size_t)b * L_ + x) * 128 + t] + w2[(size_t)1024 * 128 + t];
    __syncthreads();

    // stage S[y][o] fp32, row stride 132 floats
    float* S = (float*)smem;
#pragma unroll
    for (int mt = 0; mt < 4; mt++) {
        const int o = wm * 64 + mt * 16 + g;
        const float pb0 = pb_s[o], pb1 = pb_s[o + 8];
#pragma unroll
        for (int nt = 0; nt < 4; nt++) {
            const int y = wn * 32 + nt * 8 + qp * 2;
            S[y * 132 + o]           = acc[mt][nt][0] + pb0;
            S[(y + 1) * 132 + o]     = acc[mt][nt][1] + pb0;
            S[y * 132 + o + 8]       = acc[mt][nt][2] + pb1;
            S[(y + 1) * 132 + o + 8] = acc[mt][nt][3] + pb1;
        }
    }
    __syncthreads();
#pragma unroll
    for (int i = 0; i < 16; i++) {
        const int task = t + i * 256;
        const int y = task >> 5, oq = task & 31;
        float4 v = *(float4*)&S[y * 132 + oq * 4];
        *(float4*)(out + (((size_t)b * L_ + x) * L_ + n0 + y) * 128 + oq * 4) = v;
    }
}

// -------------------- conversion kernels --------------------
__global__ __launch_bounds__(256) void cvt_kernel(const float* __restrict__ in1,
                                                  const float* __restrict__ in2) {
    const int i = blockIdx.x * 256 + threadIdx.x;   // float4 index
    const int which = blockIdx.y;
    const float* src = which ? in2 : in1;
    float4 v = ((const float4*)src)[i];
    half2 h0 = __floats2half2_rn(v.x, v.y);
    half2 h1 = __floats2half2_rn(v.z, v.w);
    hf* dh = which ? g_I2hi : g_Ahi;
    ((half2*)dh)[2 * i] = h0;
    ((half2*)dh)[2 * i + 1] = h1;
}

// w1 (512 x 65536) -> Whi[n][k] fp16 transposed
__global__ __launch_bounds__(256) void w1t_kernel(const float* __restrict__ w1) {
    __shared__ float sm[64][33];
    const int n0 = blockIdx.x * 32;
    const int k0 = blockIdx.y * 64;
    const int t = threadIdx.x;
#pragma unroll
    for (int it = 0; it < 8; it++) {
        const int idx = t + it * 256;
        const int i = idx >> 5, j = idx & 31;
        sm[i][j] = w1[(size_t)(k0 + i) * 65536 + n0 + j];
    }
    __syncthreads();
    const int n = t >> 3, kq = t & 7;
    hf h[8];
#pragma unroll
    for (int u = 0; u < 8; u++) h[u] = __float2half_rn(sm[kq * 8 + u][n]);
    *(uint4*)(g_Whi + (size_t)(n0 + n) * 512 + k0 + kq * 8) = *(uint4*)h;
}

// w2 (1025 x 128) -> W2aT[o][i] fp16, W2bT[o][j] fp32
__global__ __launch_bounds__(256) void w2t_kernel(const float* __restrict__ w2) {
    const int idx = blockIdx.x * 256 + threadIdx.x;   // 0..65535
    const int o = idx & 127, k = idx >> 7;            // coalesced reads over o
    const float a = w2[(size_t)k * 128 + o];
    const float b = w2[(size_t)(512 + k) * 128 + o];
    g_W2aT[o * 512 + k] = __float2half_rn(a);
    g_W2bT[o * 512 + k] = b;
}

// -------------------- host --------------------
extern "C" void kernel_launch(void* const* d_in, const int* in_sizes, int n_in,
                              void* d_out, int out_size) {
    const float* in1 = (const float*)d_in[0];
    const float* in2 = (const float*)d_in[1];
    const float* w1  = (const float*)d_in[2];
    const float* w2  = (const float*)d_in[3];
    float* out = (float*)d_out;

    cudaFuncSetAttribute(stage1_mma, cudaFuncAttributeMaxDynamicSharedMemorySize, SMEM_BYTES);
    cudaFuncSetAttribute(stage2_mma, cudaFuncAttributeMaxDynamicSharedMemorySize, SMEM_BYTES);

    cvt_kernel<<<dim3(2048 * 512 / 4 / 256, 2), 256>>>(in1, in2);
    w2t_kernel<<<65536 / 256, 256>>>(w2);
    w1t_kernel<<<dim3(65536 / 32, 512 / 64), 256>>>(w1);

    stage1_mma<<<dim3(16, 513), 256, SMEM_BYTES>>>();
    stage2_mma<<<dim3(2, 256, 8), 256, SMEM_BYTES>>>(w2, out);
}

// round 14
// speedup vs baseline: 1.1892x; 1.1892x over previous
#include <cuda_runtime.h>
#include <cuda_fp16.h>
#include <cstdint>
#include <cstddef>

// Biaffine: out[b,x,y,o] = sum_ij in1[b,x,i] w1[i,o,j] in2[b,y,j] + p + q + bias
//   stage1: U' = in1_hi @ w1_hi^T (+ w2b^T folded -> q) ; p-tile = in1 @ w2a
//   stage2: out = U' @ in2_hi^T + (p + bias)
// mma.sync.m16n8k16 fp16 fp32-acc; CTA 128x128 (128 thr, 4 warps 2x2, 2 CTA/SM),
// K-chunk 64, 3-buf cp.async ring, register fragment double-buffer.
// Warp phase-rotation: odd warps process kst order rotated by 2 (desynchronizes
// LDSM vs HMMA phases across warps -> both pipes fed concurrently).

#define B_ 8
#define L_ 256
#define D_ 512
#define O_ 128
#define NCH 8                   // 512 / 64
#define TBUF 18432              // 128 rows * 144B
#define CBUF (2 * TBUF)         // A + B tiles per chunk buffer
#define SMEM_BYTES 110592       // 3 * CBUF (epilogues fit inside)

using hf = __half;

// -------------------- device globals (no runtime alloc) --------------------
__device__ __align__(128) hf g_Ahi[2048 * 512];
__device__ __align__(128) hf g_I2hi[2048 * 512];
__device__ __align__(128) hf g_Whi[(size_t)65536 * 512];
__device__ __align__(128) hf g_Uhi[(size_t)262144 * 512];
__device__ __align__(128) hf g_W2aT[128 * 512];     // [o][i] fp16 (p-tile B operand)
__device__ __align__(128) float g_W2bT[128 * 512];  // [o][j] fp32 (U epilogue addend)
__device__ __align__(128) float g_p[2048 * 128];

// -------------------- helpers --------------------
__device__ __forceinline__ uint32_t smem_u32(const void* p) {
    uint32_t a;
    asm("{ .reg .u64 t; cvta.to.shared.u64 t, %1; cvt.u32.u64 %0, t; }" : "=r"(a) : "l"(p));
    return a;
}
__device__ __forceinline__ void cpa16(uint32_t s, const void* g) {
    asm volatile("cp.async.cg.shared.global [%0], [%1], 16;" :: "r"(s), "l"(g));
}
#define CP_COMMIT asm volatile("cp.async.commit_group;" ::: "memory")
#define CP_WAIT1  asm volatile("cp.async.wait_group 1;" ::: "memory")
#define CP_WAIT0  asm volatile("cp.async.wait_group 0;" ::: "memory")
#define CP_WAIT2  asm volatile("cp.async.wait_group 2;" ::: "memory")

__device__ __forceinline__ void ldmx4(uint32_t* r, uint32_t addr) {
    asm volatile("ldmatrix.sync.aligned.m8n8.x4.shared.b16 {%0,%1,%2,%3}, [%4];"
                 : "=r"(r[0]), "=r"(r[1]), "=r"(r[2]), "=r"(r[3]) : "r"(addr));
}
__device__ __forceinline__ void mma16816(float* c, const uint32_t* a, uint32_t b0, uint32_t b1) {
    asm("mma.sync.aligned.m16n8k16.row.col.f32.f16.f16.f32 "
        "{%0,%1,%2,%3},{%4,%5,%6,%7},{%8,%9},{%0,%1,%2,%3};"
        : "+f"(c[0]), "+f"(c[1]), "+f"(c[2]), "+f"(c[3])
        : "r"(a[0]), "r"(a[1]), "r"(a[2]), "r"(a[3]), "r"(b0), "r"(b1));
}

// -------------------- chunk loader: A + B tiles 128x64 fp16 (144B stride) ---
__device__ __forceinline__ void load2(uint32_t sbase, int buf,
                                      const hf* __restrict__ ta,
                                      const hf* __restrict__ tb,
                                      int kcol, int t) {
    const int r = t >> 3, c = t & 7;               // r 0..15, c 0..7 (16B units)
    const uint32_t so = sbase + buf * CBUF + r * 144 + c * 16;
    const size_t go = (size_t)r * 512 + kcol + c * 8;
    const hf* ga = ta + go;
    const hf* gb = tb + go;
#pragma unroll
    for (int p = 0; p < 8; p++) cpa16(so + p * (16 * 144), ga + (size_t)16 * p * 512);
#pragma unroll
    for (int p = 0; p < 8; p++) cpa16(so + TBUF + p * (16 * 144), gb + (size_t)16 * p * 512);
}

// -------------------- fragment load + mma --------------------
__device__ __forceinline__ void ld_frags(uint32_t sbase, int buf, int kst,
                                         int wm, int wn, uint32_t lro,
                                         uint32_t ar[4][4], uint32_t br[4][4]) {
    const uint32_t sA = sbase + buf * CBUF + wm * (64 * 144) + lro + kst * 32;
    const uint32_t sB = sbase + buf * CBUF + TBUF + wn * (64 * 144) + lro + kst * 32;
#pragma unroll
    for (int mt = 0; mt < 4; mt++) ldmx4(ar[mt], sA + mt * (16 * 144));
#pragma unroll
    for (int n2 = 0; n2 < 4; n2++) ldmx4(br[n2], sB + n2 * (16 * 144));
}
__device__ __forceinline__ void do_mma(float acc[4][8][4],
                                       uint32_t ar[4][4], uint32_t br[4][4]) {
#pragma unroll
    for (int mt = 0; mt < 4; mt++)
#pragma unroll
        for (int n2 = 0; n2 < 4; n2++) {
            mma16816(acc[mt][n2 * 2 + 0], ar[mt], br[n2][0], br[n2][2]);
            mma16816(acc[mt][n2 * 2 + 1], ar[mt], br[n2][1], br[n2][3]);
        }
}

// -------------------- shared mainloop (CTA 128x128, warps 2x2, 64x64) ------
// One barrier per 64-wide K-chunk; frags double-buffered over 4 kst steps.
// krot (0 or 2, per warp) rotates the kst visit order inside each chunk.
__device__ __forceinline__ void mma_mainloop(char* smem,
                                             const hf* pa, const hf* pb,
                                             float acc[4][8][4],
                                             int wm, int wn, int lane, int t,
                                             int krot) {
    const uint32_t sbase = smem_u32(smem);
    const uint32_t lro = (lane & 15) * 144 + (lane >> 4) * 16;

    uint32_t a0[4][4], b0[4][4], a1[4][4], b1[4][4];

    load2(sbase, 0, pa, pb, 0, t);   CP_COMMIT;
    load2(sbase, 1, pa, pb, 64, t);  CP_COMMIT;
    load2(sbase, 2, pa, pb, 128, t); CP_COMMIT;
    CP_WAIT2;                 // buf0 complete
    __syncthreads();
    ld_frags(sbase, 0, 0 ^ krot, wm, wn, lro, a0, b0);

#pragma unroll
    for (int c = 0; c < NCH; c++) {
        const int buf = c % 3;
        ld_frags(sbase, buf, 1 ^ krot, wm, wn, lro, a1, b1);
        do_mma(acc, a0, b0);
        ld_frags(sbase, buf, 2 ^ krot, wm, wn, lro, a0, b0);
        do_mma(acc, a1, b1);
        ld_frags(sbase, buf, 3 ^ krot, wm, wn, lro, a1, b1);
        do_mma(acc, a0, b0);

        if (c + 1 < NCH) {
            if (c == NCH - 2) { CP_WAIT0; } else { CP_WAIT1; }
            __syncthreads();   // all warps done reading buf c
            ld_frags(sbase, (c + 1) % 3, 0 ^ krot, wm, wn, lro, a0, b0);
            do_mma(acc, a1, b1);
            if (c + 3 < NCH) { load2(sbase, (c + 3) % 3, pa, pb, (c + 3) * 64, t); CP_COMMIT; }
        } else {
            do_mma(acc, a1, b1);
        }
    }
}

// -------------------- stage 1: U' = Ahi @ Whi^T + w2b^T; p-tile at by==512 --
// grid (16, 513): x = m-tile (2048/128), y = n-tile (65536/128) or p-tile
__global__ __launch_bounds__(128, 2) void stage1_mma() {
    extern __shared__ char smem[];
    const int t = threadIdx.x, lane = t & 31, wid = t >> 5;
    const int wm = wid & 1, wn = wid >> 1;
    const int g = lane >> 2, qp = lane & 3;
    const int krot = (wid & 1) * 2;

    const size_t m0 = (size_t)blockIdx.x * 128;
    const int by = blockIdx.y;
    const bool ptile = (by == 512);
    const int n0 = ptile ? 0 : by * 128;
    const int o = n0 >> 9, j0 = n0 & 511;

    float acc[4][8][4];
#pragma unroll
    for (int i = 0; i < 4; i++)
#pragma unroll
        for (int j = 0; j < 8; j++)
#pragma unroll
            for (int k = 0; k < 4; k++) acc[i][j][k] = 0.f;

    const hf* pb = ptile ? g_W2aT : (g_Whi + (size_t)n0 * 512);
    mma_mainloop(smem, g_Ahi + m0 * 512, pb, acc, wm, wn, lane, t, krot);

    if (ptile) {
        // p[m][o] = acc, fp32 direct stores (16 CTAs total, cost negligible)
#pragma unroll
        for (int mt = 0; mt < 4; mt++) {
            const int r = wm * 64 + mt * 16 + g;
#pragma unroll
            for (int nt = 0; nt < 8; nt++) {
                const int col = wn * 64 + nt * 8 + qp * 2;
                float* d0 = &g_p[(m0 + r) * 128 + col];
                d0[0] = acc[mt][nt][0];
                d0[1] = acc[mt][nt][1];
                float* d1 = &g_p[(m0 + r + 8) * 128 + col];
                d1[0] = acc[mt][nt][2];
                d1[1] = acc[mt][nt][3];
            }
        }
        return;
    }

    // fold q: add w2b^T[o][j0+col] (col-only dependent, 16 values per thread)
    float wb[8][2];
#pragma unroll
    for (int nt = 0; nt < 8; nt++) {
        const int col = wn * 64 + nt * 8 + qp * 2;
        wb[nt][0] = g_W2bT[o * 512 + j0 + col];
        wb[nt][1] = g_W2bT[o * 512 + j0 + col + 1];
    }

    // epilogue: fp32 acc (+w2b) -> fp16, staged in smem (272B stride)
    __syncthreads();
#pragma unroll
    for (int mt = 0; mt < 4; mt++) {
        const int r = wm * 64 + mt * 16 + g;
#pragma unroll
        for (int nt = 0; nt < 8; nt++) {
            const int col = wn * 64 + nt * 8 + qp * 2;
            *(half2*)(smem + r * 272 + col * 2) =
                __floats2half2_rn(acc[mt][nt][0] + wb[nt][0], acc[mt][nt][1] + wb[nt][1]);
            *(half2*)(smem + (r + 8) * 272 + col * 2) =
                __floats2half2_rn(acc[mt][nt][2] + wb[nt][0], acc[mt][nt][3] + wb[nt][1]);
        }
    }
    __syncthreads();
#pragma unroll
    for (int i = 0; i < 16; i++) {
        const int idx = t + i * 128;
        const int r = idx >> 4, colq = idx & 15;
        uint4 v = *(uint4*)(smem + r * 272 + colq * 16);
        *(uint4*)(g_Uhi + ((m0 + r) * 128 + o) * 512 + j0 + colq * 8) = v;
    }
}

// -------------------- stage 2: out = U' @ I2hi^T + (p + bias) ----
// grid (2, 256, 8): x = y-tile, y = x index, z = b
__global__ __launch_bounds__(128, 2) void stage2_mma(const float* __restrict__ w2,
                                                     float* __restrict__ out) {
    extern __shared__ char smem[];
    __shared__ float pb_s[128];
    const int t = threadIdx.x, lane = t & 31, wid = t >> 5;
    const int wm = wid & 1, wn = wid >> 1;
    const int g = lane >> 2, qp = lane & 3;
    const int krot = (wid & 1) * 2;

    const int b = blockIdx.z, x = blockIdx.y, n0 = blockIdx.x * 128;
    const size_t a_row0 = ((size_t)b * L_ + x) * 128;   // U rows (o)
    const size_t b_row0 = (size_t)b * L_ + n0;          // in2 rows (y)

    float acc[4][8][4];
#pragma unroll
    for (int i = 0; i < 4; i++)
#pragma unroll
        for (int j = 0; j < 8; j++)
#pragma unroll
            for (int k = 0; k < 4; k++) acc[i][j][k] = 0.f;

    mma_mainloop(smem, g_Uhi + a_row0 * 512, g_I2hi + b_row0 * 512, acc, wm, wn, lane, t, krot);

    __syncthreads();
    if (t < 128) pb_s[t] = g_p[((size_t)b * L_ + x) * 128 + t] + w2[(size_t)1024 * 128 + t];
    __syncthreads();

    // stage S[y][o] fp32, row stride 132 floats (conflict-free writes, uint4 reads)
    float* S = (float*)smem;
#pragma unroll
    for (int mt = 0; mt < 4; mt++) {
        const int o = wm * 64 + mt * 16 + g;
        const float pb0 = pb_s[o], pb1 = pb_s[o + 8];
#pragma unroll
        for (int nt = 0; nt < 8; nt++) {
            const int y = wn * 64 + nt * 8 + qp * 2;
            S[y * 132 + o]           = acc[mt][nt][0] + pb0;
            S[(y + 1) * 132 + o]     = acc[mt][nt][1] + pb0;
            S[y * 132 + o + 8]       = acc[mt][nt][2] + pb1;
            S[(y + 1) * 132 + o + 8] = acc[mt][nt][3] + pb1;
        }
    }
    __syncthreads();
#pragma unroll
    for (int i = 0; i < 32; i++) {
        const int task = t + i * 128;
        const int y = task >> 5, oq = task & 31;
        float4 v = *(float4*)&S[y * 132 + oq * 4];
        *(float4*)(out + (((size_t)b * L_ + x) * L_ + n0 + y) * 128 + oq * 4) = v;
    }
}

// -------------------- conversion kernels --------------------
__global__ __launch_bounds__(256) void cvt_kernel(const float* __restrict__ in1,
                                                  const float* __restrict__ in2) {
    const int i = blockIdx.x * 256 + threadIdx.x;   // float4 index
    const int which = blockIdx.y;
    const float* src = which ? in2 : in1;
    float4 v = ((const float4*)src)[i];
    half2 h0 = __floats2half2_rn(v.x, v.y);
    half2 h1 = __floats2half2_rn(v.z, v.w);
    hf* dh = which ? g_I2hi : g_Ahi;
    ((half2*)dh)[2 * i] = h0;
    ((half2*)dh)[2 * i + 1] = h1;
}

// w1 (512 x 65536) -> Whi[n][k] fp16 transposed
__global__ __launch_bounds__(256) void w1t_kernel(const float* __restrict__ w1) {
    __shared__ float sm[64][33];
    const int n0 = blockIdx.x * 32;
    const int k0 = blockIdx.y * 64;
    const int t = threadIdx.x;
#pragma unroll
    for (int it = 0; it < 8; it++) {
        const int idx = t + it * 256;
        const int i = idx >> 5, j = idx & 31;
        sm[i][j] = w1[(size_t)(k0 + i) * 65536 + n0 + j];
    }
    __syncthreads();
    const int n = t >> 3, kq = t & 7;
    hf h[8];
#pragma unroll
    for (int u = 0; u < 8; u++) h[u] = __float2half_rn(sm[kq * 8 + u][n]);
    *(uint4*)(g_Whi + (size_t)(n0 + n) * 512 + k0 + kq * 8) = *(uint4*)h;
}

// w2 (1025 x 128) -> W2aT[o][i] fp16, W2bT[o][j] fp32
__global__ __launch_bounds__(256) void w2t_kernel(const float* __restrict__ w2) {
    const int idx = blockIdx.x * 256 + threadIdx.x;   // 0..65535
    const int o = idx & 127, k = idx >> 7;            // coalesced reads over o
    const float a = w2[(size_t)k * 128 + o];
    const float b = w2[(size_t)(512 + k) * 128 + o];
    g_W2aT[o * 512 + k] = __float2half_rn(a);
    g_W2bT[o * 512 + k] = b;
}

// -------------------- host --------------------
extern "C" void kernel_launch(void* const* d_in, const int* in_sizes, int n_in,
                              void* d_out, int out_size) {
    const float* in1 = (const float*)d_in[0];
    const float* in2 = (const float*)d_in[1];
    const float* w1  = (const float*)d_in[2];
    const float* w2  = (const float*)d_in[3];
    float* out = (float*)d_out;

    cudaFuncSetAttribute(stage1_mma, cudaFuncAttributeMaxDynamicSharedMemorySize, SMEM_BYTES);
    cudaFuncSetAttribute(stage2_mma, cudaFuncAttributeMaxDynamicSharedMemorySize, SMEM_BYTES);

    cvt_kernel<<<dim3(2048 * 512 / 4 / 256, 2), 256>>>(in1, in2);
    w2t_kernel<<<65536 / 256, 256>>>(w2);
    w1t_kernel<<<dim3(65536 / 32, 512 / 64), 256>>>(w1);

    stage1_mma<<<dim3(16, 513), 128, SMEM_BYTES>>>();
    stage2_mma<<<dim3(2, 256, 8), 128, SMEM_BYTES>>>(w2, out);
}

// round 15
// speedup vs baseline: 1.2086x; 1.0164x over previous
#include <cuda_runtime.h>
#include <cuda_fp16.h>
#include <cstdint>
#include <cstddef>

// Biaffine: out[b,x,y,o] = sum_ij in1[b,x,i] w1[i,o,j] in2[b,y,j] + p + q + bias
//   stage1: U' = in1_hi @ w1_hi^T (+ w2b^T folded -> q) ; p-tile = in1 @ w2a
//   stage2: out = U' @ in2_hi^T + (p + bias)
// mma.sync.m16n8k16 fp16 fp32-acc (measured at the sm_103a SIMT HMMA rate
// ceiling ~305 TF/s); CTA 128x128 (128 thr, 4 warps 2x2, 2 CTA/SM),
// K-chunk 64, 3-buf cp.async ring, register fragment double-buffer.
// All pre-work (w1 transpose+cvt, input cvt, w2 split) fused into ONE kernel.

#define B_ 8
#define L_ 256
#define D_ 512
#define O_ 128
#define NCH 8                   // 512 / 64
#define TBUF 18432              // 128 rows * 144B
#define CBUF (2 * TBUF)         // A + B tiles per chunk buffer
#define SMEM_BYTES 110592       // 3 * CBUF (epilogues fit inside)

using hf = __half;

// -------------------- device globals (no runtime alloc) --------------------
__device__ __align__(128) hf g_Ahi[2048 * 512];
__device__ __align__(128) hf g_I2hi[2048 * 512];
__device__ __align__(128) hf g_Whi[(size_t)65536 * 512];
__device__ __align__(128) hf g_Uhi[(size_t)262144 * 512];
__device__ __align__(128) hf g_W2aT[128 * 512];     // [o][i] fp16 (p-tile B operand)
__device__ __align__(128) float g_W2bT[128 * 512];  // [o][j] fp32 (U epilogue addend)
__device__ __align__(128) float g_p[2048 * 128];

// -------------------- helpers --------------------
__device__ __forceinline__ uint32_t smem_u32(const void* p) {
    uint32_t a;
    asm("{ .reg .u64 t; cvta.to.shared.u64 t, %1; cvt.u32.u64 %0, t; }" : "=r"(a) : "l"(p));
    return a;
}
__device__ __forceinline__ void cpa16(uint32_t s, const void* g) {
    asm volatile("cp.async.cg.shared.global [%0], [%1], 16;" :: "r"(s), "l"(g));
}
#define CP_COMMIT asm volatile("cp.async.commit_group;" ::: "memory")
#define CP_WAIT2  asm volatile("cp.async.wait_group 2;" ::: "memory")
#define CP_WAIT1  asm volatile("cp.async.wait_group 1;" ::: "memory")
#define CP_WAIT0  asm volatile("cp.async.wait_group 0;" ::: "memory")

__device__ __forceinline__ void ldmx4(uint32_t* r, uint32_t addr) {
    asm volatile("ldmatrix.sync.aligned.m8n8.x4.shared.b16 {%0,%1,%2,%3}, [%4];"
                 : "=r"(r[0]), "=r"(r[1]), "=r"(r[2]), "=r"(r[3]) : "r"(addr));
}
__device__ __forceinline__ void mma16816(float* c, const uint32_t* a, uint32_t b0, uint32_t b1) {
    asm("mma.sync.aligned.m16n8k16.row.col.f32.f16.f16.f32 "
        "{%0,%1,%2,%3},{%4,%5,%6,%7},{%8,%9},{%0,%1,%2,%3};"
        : "+f"(c[0]), "+f"(c[1]), "+f"(c[2]), "+f"(c[3])
        : "r"(a[0]), "r"(a[1]), "r"(a[2]), "r"(a[3]), "r"(b0), "r"(b1));
}

// -------------------- chunk loader: A + B tiles 128x64 fp16 (144B stride) ---
__device__ __forceinline__ void load2(uint32_t sbase, int buf,
                                      const hf* __restrict__ ta,
                                      const hf* __restrict__ tb,
                                      int kcol, int t) {
    const int r = t >> 3, c = t & 7;               // r 0..15, c 0..7 (16B units)
    const uint32_t so = sbase + buf * CBUF + r * 144 + c * 16;
    const size_t go = (size_t)r * 512 + kcol + c * 8;
    const hf* ga = ta + go;
    const hf* gb = tb + go;
#pragma unroll
    for (int p = 0; p < 8; p++) cpa16(so + p * (16 * 144), ga + (size_t)16 * p * 512);
#pragma unroll
    for (int p = 0; p < 8; p++) cpa16(so + TBUF + p * (16 * 144), gb + (size_t)16 * p * 512);
}

// -------------------- fragment load + mma --------------------
__device__ __forceinline__ void ld_frags(uint32_t sbase, int buf, int kst,
                                         int wm, int wn, uint32_t lro,
                                         uint32_t ar[4][4], uint32_t br[4][4]) {
    const uint32_t sA = sbase + buf * CBUF + wm * (64 * 144) + lro + kst * 32;
    const uint32_t sB = sbase + buf * CBUF + TBUF + wn * (64 * 144) + lro + kst * 32;
#pragma unroll
    for (int mt = 0; mt < 4; mt++) ldmx4(ar[mt], sA + mt * (16 * 144));
#pragma unroll
    for (int n2 = 0; n2 < 4; n2++) ldmx4(br[n2], sB + n2 * (16 * 144));
}
__device__ __forceinline__ void do_mma(float acc[4][8][4],
                                       uint32_t ar[4][4], uint32_t br[4][4]) {
#pragma unroll
    for (int mt = 0; mt < 4; mt++)
#pragma unroll
        for (int n2 = 0; n2 < 4; n2++) {
            mma16816(acc[mt][n2 * 2 + 0], ar[mt], br[n2][0], br[n2][2]);
            mma16816(acc[mt][n2 * 2 + 1], ar[mt], br[n2][1], br[n2][3]);
        }
}

// -------------------- shared mainloop (CTA 128x128, warps 2x2, 64x64) ------
// One barrier per 64-wide K-chunk; frags double-buffered over 4 kst steps.
__device__ __forceinline__ void mma_mainloop(char* smem,
                                             const hf* pa, const hf* pb,
                                             float acc[4][8][4],
                                             int wm, int wn, int lane, int t) {
    const uint32_t sbase = smem_u32(smem);
    const uint32_t lro = (lane & 15) * 144 + (lane >> 4) * 16;

    uint32_t a0[4][4], b0[4][4], a1[4][4], b1[4][4];

    load2(sbase, 0, pa, pb, 0, t);   CP_COMMIT;
    load2(sbase, 1, pa, pb, 64, t);  CP_COMMIT;
    load2(sbase, 2, pa, pb, 128, t); CP_COMMIT;
    CP_WAIT2;                 // buf0 complete
    __syncthreads();
    ld_frags(sbase, 0, 0, wm, wn, lro, a0, b0);

#pragma unroll
    for (int c = 0; c < NCH; c++) {
        const int buf = c % 3;
        ld_frags(sbase, buf, 1, wm, wn, lro, a1, b1);
        do_mma(acc, a0, b0);
        ld_frags(sbase, buf, 2, wm, wn, lro, a0, b0);
        do_mma(acc, a1, b1);
        ld_frags(sbase, buf, 3, wm, wn, lro, a1, b1);
        do_mma(acc, a0, b0);

        if (c + 1 < NCH) {
            if (c == NCH - 2) { CP_WAIT0; } else { CP_WAIT1; }
            __syncthreads();   // all warps done reading buf c
            ld_frags(sbase, (c + 1) % 3, 0, wm, wn, lro, a0, b0);
            do_mma(acc, a1, b1);
            if (c + 3 < NCH) { load2(sbase, (c + 3) % 3, pa, pb, (c + 3) * 64, t); CP_COMMIT; }
        } else {
            do_mma(acc, a1, b1);
        }
    }
}

// -------------------- stage 1: U' = Ahi @ Whi^T + w2b^T; p-tile at by==512 --
// grid (16, 513): x = m-tile (2048/128), y = n-tile (65536/128) or p-tile
__global__ __launch_bounds__(128, 2) void stage1_mma() {
    extern __shared__ char smem[];
    const int t = threadIdx.x, lane = t & 31, wid = t >> 5;
    const int wm = wid & 1, wn = wid >> 1;
    const int g = lane >> 2, qp = lane & 3;

    const size_t m0 = (size_t)blockIdx.x * 128;
    const int by = blockIdx.y;
    const bool ptile = (by == 512);
    const int n0 = ptile ? 0 : by * 128;
    const int o = n0 >> 9, j0 = n0 & 511;

    float acc[4][8][4];
#pragma unroll
    for (int i = 0; i < 4; i++)
#pragma unroll
        for (int j = 0; j < 8; j++)
#pragma unroll
            for (int k = 0; k < 4; k++) acc[i][j][k] = 0.f;

    const hf* pb = ptile ? g_W2aT : (g_Whi + (size_t)n0 * 512);
    mma_mainloop(smem, g_Ahi + m0 * 512, pb, acc, wm, wn, lane, t);

    if (ptile) {
        // p[m][o] = acc, fp32 direct stores (16 CTAs total, cost negligible)
#pragma unroll
        for (int mt = 0; mt < 4; mt++) {
            const int r = wm * 64 + mt * 16 + g;
#pragma unroll
            for (int nt = 0; nt < 8; nt++) {
                const int col = wn * 64 + nt * 8 + qp * 2;
                float* d0 = &g_p[(m0 + r) * 128 + col];
                d0[0] = acc[mt][nt][0];
                d0[1] = acc[mt][nt][1];
                float* d1 = &g_p[(m0 + r + 8) * 128 + col];
                d1[0] = acc[mt][nt][2];
                d1[1] = acc[mt][nt][3];
            }
        }
        return;
    }

    // fold q: add w2b^T[o][j0+col] (col-only dependent, 16 values per thread)
    float wb[8][2];
#pragma unroll
    for (int nt = 0; nt < 8; nt++) {
        const int col = wn * 64 + nt * 8 + qp * 2;
        wb[nt][0] = g_W2bT[o * 512 + j0 + col];
        wb[nt][1] = g_W2bT[o * 512 + j0 + col + 1];
    }

    // epilogue: fp32 acc (+w2b) -> fp16, staged in smem (272B stride)
    __syncthreads();
#pragma unroll
    for (int mt = 0; mt < 4; mt++) {
        const int r = wm * 64 + mt * 16 + g;
#pragma unroll
        for (int nt = 0; nt < 8; nt++) {
            const int col = wn * 64 + nt * 8 + qp * 2;
            *(half2*)(smem + r * 272 + col * 2) =
                __floats2half2_rn(acc[mt][nt][0] + wb[nt][0], acc[mt][nt][1] + wb[nt][1]);
            *(half2*)(smem + (r + 8) * 272 + col * 2) =
                __floats2half2_rn(acc[mt][nt][2] + wb[nt][0], acc[mt][nt][3] + wb[nt][1]);
        }
    }
    __syncthreads();
#pragma unroll
    for (int i = 0; i < 16; i++) {
        const int idx = t + i * 128;
        const int r = idx >> 4, colq = idx & 15;
        uint4 v = *(uint4*)(smem + r * 272 + colq * 16);
        *(uint4*)(g_Uhi + ((m0 + r) * 128 + o) * 512 + j0 + colq * 8) = v;
    }
}

// -------------------- stage 2: out = U' @ I2hi^T + (p + bias) ----
// grid (2, 256, 8): x = y-tile, y = x index, z = b
__global__ __launch_bounds__(128, 2) void stage2_mma(const float* __restrict__ w2,
                                                     float* __restrict__ out) {
    extern __shared__ char smem[];
    __shared__ float pb_s[128];
    const int t = threadIdx.x, lane = t & 31, wid = t >> 5;
    const int wm = wid & 1, wn = wid >> 1;
    const int g = lane >> 2, qp = lane & 3;

    const int b = blockIdx.z, x = blockIdx.y, n0 = blockIdx.x * 128;
    const size_t a_row0 = ((size_t)b * L_ + x) * 128;   // U rows (o)
    const size_t b_row0 = (size_t)b * L_ + n0;          // in2 rows (y)

    float acc[4][8][4];
#pragma unroll
    for (int i = 0; i < 4; i++)
#pragma unroll
        for (int j = 0; j < 8; j++)
#pragma unroll
            for (int k = 0; k < 4; k++) acc[i][j][k] = 0.f;

    mma_mainloop(smem, g_Uhi + a_row0 * 512, g_I2hi + b_row0 * 512, acc, wm, wn, lane, t);

    __syncthreads();
    if (t < 128) pb_s[t] = g_p[((size_t)b * L_ + x) * 128 + t] + w2[(size_t)1024 * 128 + t];
    __syncthreads();

    // stage S[y][o] fp32, row stride 132 floats (conflict-free writes, uint4 reads)
    float* S = (float*)smem;
#pragma unroll
    for (int mt = 0; mt < 4; mt++) {
        const int o = wm * 64 + mt * 16 + g;
        const float pb0 = pb_s[o], pb1 = pb_s[o + 8];
#pragma unroll
        for (int nt = 0; nt < 8; nt++) {
            const int y = wn * 64 + nt * 8 + qp * 2;
            S[y * 132 + o]           = acc[mt][nt][0] + pb0;
            S[(y + 1) * 132 + o]     = acc[mt][nt][1] + pb0;
            S[y * 132 + o + 8]       = acc[mt][nt][2] + pb1;
            S[(y + 1) * 132 + o + 8] = acc[mt][nt][3] + pb1;
        }
    }
    __syncthreads();
#pragma unroll
    for (int i = 0; i < 32; i++) {
        const int task = t + i * 128;
        const int y = task >> 5, oq = task & 31;
        float4 v = *(float4*)&S[y * 132 + oq * 4];
        *(float4*)(out + (((size_t)b * L_ + x) * L_ + n0 + y) * 128 + oq * 4) = v;
    }
}

// -------------------- unified prep kernel --------------------
// grid x layout (256 thr each):
//   [0, 16384)        w1 transpose+cvt: n-tile = bx & 2047, k-tile = bx >> 11
//   [16384, 17408)    cvt in1 -> g_Ahi
//   [17408, 18432)    cvt in2 -> g_I2hi
//   [18432, 18688)    w2 split -> g_W2aT (fp16) / g_W2bT (fp32)
__global__ __launch_bounds__(256) void prep_kernel(const float* __restrict__ w1,
                                                   const float* __restrict__ in1,
                                                   const float* __restrict__ in2,
                                                   const float* __restrict__ w2) {
    const int bx = blockIdx.x, t = threadIdx.x;

    if (bx < 16384) {
        __shared__ float sm[64][33];
        const int n0 = (bx & 2047) * 32;
        const int k0 = (bx >> 11) * 64;
#pragma unroll
        for (int it = 0; it < 8; it++) {
            const int idx = t + it * 256;
            const int i = idx >> 5, j = idx & 31;
            sm[i][j] = w1[(size_t)(k0 + i) * 65536 + n0 + j];
        }
        __syncthreads();
        const int n = t >> 3, kq = t & 7;
        hf h[8];
#pragma unroll
        for (int u = 0; u < 8; u++) h[u] = __float2half_rn(sm[kq * 8 + u][n]);
        *(uint4*)(g_Whi + (size_t)(n0 + n) * 512 + k0 + kq * 8) = *(uint4*)h;
    } else if (bx < 18432) {
        const int which = (bx >= 17408);
        const int i = (bx - (which ? 17408 : 16384)) * 256 + t;   // float4 index
        const float* src = which ? in2 : in1;
        float4 v = ((const float4*)src)[i];
        half2 h0 = __floats2half2_rn(v.x, v.y);
        half2 h1 = __floats2half2_rn(v.z, v.w);
        hf* dh = which ? g_I2hi : g_Ahi;
        ((half2*)dh)[2 * i] = h0;
        ((half2*)dh)[2 * i + 1] = h1;
    } else {
        const int idx = (bx - 18432) * 256 + t;   // 0..65535
        const int o = idx & 127, k = idx >> 7;    // coalesced reads over o
        const float a = w2[(size_t)k * 128 + o];
        const float b = w2[(size_t)(512 + k) * 128 + o];
        g_W2aT[o * 512 + k] = __float2half_rn(a);
        g_W2bT[o * 512 + k] = b;
    }
}

// -------------------- host --------------------
extern "C" void kernel_launch(void* const* d_in, const int* in_sizes, int n_in,
                              void* d_out, int out_size) {
    const float* in1 = (const float*)d_in[0];
    const float* in2 = (const float*)d_in[1];
    const float* w1  = (const float*)d_in[2];
    const float* w2  = (const float*)d_in[3];
    float* out = (float*)d_out;

    cudaFuncSetAttribute(stage1_mma, cudaFuncAttributeMaxDynamicSharedMemorySize, SMEM_BYTES);
    cudaFuncSetAttribute(stage2_mma, cudaFuncAttributeMaxDynamicSharedMemorySize, SMEM_BYTES);

    prep_kernel<<<18688, 256>>>(w1, in1, in2, w2);
    stage1_mma<<<dim3(16, 513), 128, SMEM_BYTES>>>();
    stage2_mma<<<dim3(2, 256, 8), 128, SMEM_BYTES>>>(w2, out);
}